// round 2
// baseline (speedup 1.0000x reference)
#include <cuda_runtime.h>
#include <cstdint>

#define IN_FEATURES  4096
#define OUT_FEATURES 11008
#define WORDS        (IN_FEATURES / 8)   // 512 packed int32 rows
#define BLOCK_THREADS 256
#define OUTS_PER_BLOCK 32
#define KSLICES 8
#define WORDS_PER_THREAD (WORDS / KSLICES)  // 64

// Packed constants: two fp32 lanes of -8388608.0f (0xCB000000)
#define NEG_MAGIC2 0xCB000000CB000000ull

// One packed pair of nibble-MACs:
//   lo = float(8388608 + nib_even)   from byte SEL of e
//   hi = float(8388608 + nib_odd)    from byte SEL of h
//   f2 = (lo,hi) - (2^23,2^23)       exact (Sterbenz)
//   acc2 += xpair * f2
template <unsigned SEL>
__device__ __forceinline__ void qfma2(unsigned long long& acc,
                                      unsigned e, unsigned h,
                                      unsigned long long xpair) {
    asm("{\n\t"
        ".reg .b32 lo, hi;\n\t"
        ".reg .b64 f2;\n\t"
        "prmt.b32 lo, %1, 0x4B000000, %3;\n\t"
        "prmt.b32 hi, %2, 0x4B000000, %3;\n\t"
        "mov.b64 f2, {lo, hi};\n\t"
        "add.rn.f32x2 f2, f2, %4;\n\t"
        "fma.rn.f32x2 %0, f2, %5, %0;\n\t"
        "}"
        : "+l"(acc)
        : "r"(e), "r"(h), "n"(SEL), "l"(NEG_MAGIC2), "l"(xpair));
}

__device__ __forceinline__ float2 ull_as_f2(unsigned long long a) {
    float2 r;
    r.x = __uint_as_float((unsigned)(a & 0xFFFFFFFFull));
    r.y = __uint_as_float((unsigned)(a >> 32));
    return r;
}

__global__ __launch_bounds__(BLOCK_THREADS)
void quant4linear_kernel(const float* __restrict__ x,
                         const int*   __restrict__ qweight,
                         const float* __restrict__ scales,
                         const float* __restrict__ zeros,
                         const float* __restrict__ bias,
                         float*       __restrict__ out) {
    __shared__ __align__(16) float xs[IN_FEATURES];
    __shared__ float red[BLOCK_THREADS / 32];
    __shared__ float part[KSLICES][OUTS_PER_BLOCK];

    const int tid = threadIdx.x;

    // ---- Stage x into shared + block-reduce x_sum ----
    float s = 0.0f;
    #pragma unroll
    for (int i = tid; i < IN_FEATURES; i += BLOCK_THREADS) {
        float v = x[i];
        xs[i] = v;
        s += v;
    }
    #pragma unroll
    for (int off = 16; off; off >>= 1)
        s += __shfl_down_sync(0xFFFFFFFFu, s, off);
    if ((tid & 31) == 0) red[tid >> 5] = s;
    __syncthreads();  // xs + red visible

    // ---- Main loop: lane = output channel, warp = K-slice ----
    const int o_local = tid & 31;
    const int ksl     = tid >> 5;
    const int o       = blockIdx.x * OUTS_PER_BLOCK + o_local;

    const int* wp = qweight + (ksl * WORDS_PER_THREAD) * OUT_FEATURES + o;
    // x pairs for word k live at ulonglong2 indices [2k, 2k+1]
    const ulonglong2* xp =
        reinterpret_cast<const ulonglong2*>(xs) + (ksl * WORDS_PER_THREAD) * 2;

    unsigned long long acc0 = 0, acc1 = 0, acc2 = 0, acc3 = 0;

    #pragma unroll 8
    for (int i = 0; i < WORDS_PER_THREAD; i++) {
        unsigned w = (unsigned)__ldg(wp);
        wp += OUT_FEATURES;
        unsigned e = w & 0x0F0F0F0Fu;          // even nibbles (j=0,2,4,6)
        unsigned h = (w >> 4) & 0x0F0F0F0Fu;   // odd  nibbles (j=1,3,5,7)
        ulonglong2 pa = xp[2 * i];             // (x0,x1),(x2,x3)
        ulonglong2 pb = xp[2 * i + 1];         // (x4,x5),(x6,x7)
        qfma2<0x7440u>(acc0, e, h, pa.x);
        qfma2<0x7441u>(acc1, e, h, pa.y);
        qfma2<0x7442u>(acc2, e, h, pb.x);
        qfma2<0x7443u>(acc3, e, h, pb.y);
    }

    float2 a0 = ull_as_f2(acc0), a1 = ull_as_f2(acc1);
    float2 a2 = ull_as_f2(acc2), a3 = ull_as_f2(acc3);
    float tsum = ((a0.x + a0.y) + (a1.x + a1.y)) +
                 ((a2.x + a2.y) + (a3.x + a3.y));

    part[ksl][o_local] = tsum;
    __syncthreads();

    // ---- Epilogue: reduce K-slices, apply scale/zero/bias ----
    if (tid < OUTS_PER_BLOCK) {
        float r = 0.0f;
        #pragma unroll
        for (int j = 0; j < KSLICES; j++) r += part[j][tid];

        float xsum = 0.0f;
        #pragma unroll
        for (int j = 0; j < BLOCK_THREADS / 32; j++) xsum += red[j];

        int oo = blockIdx.x * OUTS_PER_BLOCK + tid;
        out[oo] = r * scales[oo] - xsum * zeros[oo] + bias[oo];
    }
}

extern "C" void kernel_launch(void* const* d_in, const int* in_sizes, int n_in,
                              void* d_out, int out_size) {
    const float* x       = (const float*)d_in[0];
    const int*   qweight = (const int*)d_in[1];
    const float* scales  = (const float*)d_in[2];
    const float* zeros   = (const float*)d_in[3];
    const float* bias    = (const float*)d_in[4];
    float* out = (float*)d_out;

    dim3 grid(OUT_FEATURES / OUTS_PER_BLOCK);  // 344
    quant4linear_kernel<<<grid, BLOCK_THREADS>>>(x, qweight, scales, zeros,
                                                 bias, out);
}